// round 1
// baseline (speedup 1.0000x reference)
#include <cuda_runtime.h>

// CAM_43344809951340: per-sample symmetric tanh outer-product attention.
// out[b][i]    = 0.1*relu( sum_j tanh(av_i*av_j*s)*Wca[j] + av_i ),  i <  32
// out[b][i+32] = 0.1*relu( sum_j tanh(av_{i+32}*av_j*s)*Wcv[j] + av_{i+32} )
// where av = [f1_b, f2_b] (64 floats), s = 1/8.
// T is symmetric: compute each unique element once (2080 tanhs/sample instead
// of 4096) via XOR pairing inside a warp. Lane l owns rows l and l+32.

#define CAM_SCALE 0.125f   // 1/sqrt(2*32)

__device__ __forceinline__ float tanh_approx(float x) {
    float y;
    asm("tanh.approx.f32 %0, %1;" : "=f"(y) : "f"(x));
    return y;
}

__global__ __launch_bounds__(256, 8)
void cam_kernel(const float* __restrict__ f1, const float* __restrict__ f2,
                const float* __restrict__ Wca, const float* __restrict__ Wcv,
                float* __restrict__ out, int B, int nwarps)
{
    // Weight gather tables, per (m, lane):
    //  wlo[m-1][l] = { Wca[l^m],        Wcv[(l^m)+32] }  (lo-lo / hi-hi pairs)
    //  wx [m-1][l] = { Wca[(l^m)+32],   Wcv[l^m]      }  (cross-half pairs)
    __shared__ float2 wlo[31][32];
    __shared__ float2 wx[31][32];

    const int tid = threadIdx.x;
    for (int idx = tid; idx < 31 * 32; idx += blockDim.x) {
        int m = (idx >> 5) + 1;
        int l = idx & 31;
        int j = l ^ m;
        wlo[m - 1][l] = make_float2(Wca[j],      Wcv[j + 32]);
        wx [m - 1][l] = make_float2(Wca[j + 32], Wcv[j]);
    }
    __syncthreads();

    const int l = tid & 31;
    const int warp = blockIdx.x * (blockDim.x >> 5) + (tid >> 5);

    // Per-lane sample-independent weights: diagonal and the +32 offset pair.
    const float wd0 = Wca[l];       // row l,    col l
    const float wd1 = Wcv[l + 32];  // row l+32, col l+32
    const float wm0 = Wca[l + 32];  // row l,    col l+32
    const float wm1 = Wcv[l];       // row l+32, col l

    for (int b = warp; b < B; b += nwarps) {
        const float av_lo = f1[b * 32 + l];   // av[l]
        const float av_hi = f2[b * 32 + l];   // av[l+32]
        const float al = av_lo * CAM_SCALE;
        const float ah = av_hi * CAM_SCALE;

        float acc0 = av_lo;   // residual +f1 inside relu
        float acc1 = av_hi;   // residual +f2

        // Diagonal (unique per row)
        acc0 = fmaf(tanh_approx(al * av_lo), wd0, acc0);
        acc1 = fmaf(tanh_approx(ah * av_hi), wd1, acc1);

        // Pair (l, l+32): one tanh serves both rows
        const float t32 = tanh_approx(al * av_hi);
        acc0 = fmaf(t32, wm0, acc0);
        acc1 = fmaf(t32, wm1, acc1);

        #pragma unroll
        for (int m = 1; m < 32; m++) {
            // ---- lo-lo and hi-hi pairs at xor offset m ----
            // Lanes with l < l^m compute the lo-lo tanh; the partner lane
            // computes the hi-hi tanh. Each sends the av its partner needs.
            const bool lo = l < (l ^ m);
            const float send = lo ? av_hi : av_lo;
            const float x   = __shfl_xor_sync(0xffffffffu, send, m);
            const float sc  = lo ? al : ah;
            const float t   = tanh_approx(sc * x);
            const float to  = __shfl_xor_sync(0xffffffffu, t, m);
            const float tlo = lo ? t : to;   // T[l][l^m]
            const float thi = lo ? to : t;   // T[l+32][(l^m)+32]
            const float2 w  = wlo[m - 1][l];
            acc0 = fmaf(tlo, w.x, acc0);
            acc1 = fmaf(thi, w.y, acc1);

            // ---- cross-half pairs: row l with col (l^m)+32 ----
            // T_A(l) = tanh(av_lo[l]*av_hi[l^m]*s); the hi-row value
            // T[l+32][l^m] equals T_A(l^m) -> one shuffle.
            const float xh = __shfl_xor_sync(0xffffffffu, av_hi, m);
            const float ta = tanh_approx(al * xh);
            const float tb = __shfl_xor_sync(0xffffffffu, ta, m);
            const float2 w2 = wx[m - 1][l];
            acc0 = fmaf(ta, w2.x, acc0);
            acc1 = fmaf(tb, w2.y, acc1);
        }

        out[b * 64 + l]      = 0.1f * fmaxf(acc0, 0.0f);
        out[b * 64 + 32 + l] = 0.1f * fmaxf(acc1, 0.0f);
    }
}

extern "C" void kernel_launch(void* const* d_in, const int* in_sizes, int n_in,
                              void* d_out, int out_size) {
    const float* f1  = (const float*)d_in[0];
    const float* f2  = (const float*)d_in[1];
    const float* Wca = (const float*)d_in[2];
    const float* Wcv = (const float*)d_in[3];
    float* out = (float*)d_out;

    const int B = in_sizes[0] / 32;

    const int blocks = 1184;           // 8 blocks/SM * 148 SMs, persistent-ish
    const int threads = 256;           // 8 warps/block
    const int nwarps = blocks * (threads / 32);

    cam_kernel<<<blocks, threads>>>(f1, f2, Wca, Wcv, out, B, nwarps);
}

// round 2
// speedup vs baseline: 1.3646x; 1.3646x over previous
#include <cuda_runtime.h>

// CAM_43344809951340: per-sample symmetric tanh outer-product attention.
// T[i][j] = tanh(av_i*av_j*s) over symmetric 64x64; row contractions with Wca/Wcv.
// Warp-per-sample-group: lane l owns rows l and l+32 of S=8 register-batched
// samples. XOR pairing computes each unique tanh once; weight LDS amortized 8x;
// scale folded as sqrt(s) into both operands so shuffled values are pre-scaled.

#define RS      0.35355339059327379f   // sqrt(1/8)
#define S 8

__device__ int g_cam_counter;

__device__ __forceinline__ float tanhf_a(float x) {
    float y;
    asm("tanh.approx.f32 %0, %1;" : "=f"(y) : "f"(x));
    return y;
}

__global__ __launch_bounds__(128, 8)
void cam_kernel(const float* __restrict__ f1, const float* __restrict__ f2,
                const float* __restrict__ Wca, const float* __restrict__ Wcv,
                float* __restrict__ out, int B)
{
    // Per-(m,lane) weight tables (sample-invariant):
    //  wlo[m-1][l] = { Wca[l^m],      Wcv[(l^m)+32] }   lo-lo / hi-hi pairs
    //  wx [m-1][l] = { Wca[(l^m)+32], Wcv[l^m]      }   cross-half pairs
    __shared__ float2 wlo[31][32];
    __shared__ float2 wx[31][32];

    const int tid = threadIdx.x;
    for (int idx = tid; idx < 31 * 32; idx += blockDim.x) {
        int m = (idx >> 5) + 1;
        int l2 = idx & 31;
        int j = l2 ^ m;
        wlo[m - 1][l2] = make_float2(Wca[j],      Wcv[j + 32]);
        wx [m - 1][l2] = make_float2(Wca[j + 32], Wcv[j]);
    }
    __syncthreads();

    const int l = tid & 31;
    const float wd0 = Wca[l];       // diag row l
    const float wd1 = Wcv[l + 32];  // diag row l+32
    const float wm0 = Wca[l + 32];  // pair (l, l+32)
    const float wm1 = Wcv[l];       // pair (l+32, l)

    const int nbatch = (B + S - 1) / S;

    while (true) {
        int batch = 0;
        if (l == 0) batch = atomicAdd(&g_cam_counter, 1);
        batch = __shfl_sync(0xffffffffu, batch, 0);
        if (batch >= nbatch) break;
        const int base = batch * S;

        float al[S], ah[S], a0[S], a1[S];
        #pragma unroll
        for (int k = 0; k < S; k++) {
            int b = base + k;
            bool v = b < B;
            float x0 = v ? f1[b * 32 + l] : 0.0f;
            float x1 = v ? f2[b * 32 + l] : 0.0f;
            a0[k] = x0; a1[k] = x1;          // residuals / accumulators
            al[k] = x0 * RS; ah[k] = x1 * RS; // pre-scaled av halves
        }

        // Diagonal + (l, l+32) pair — no communication needed
        #pragma unroll
        for (int k = 0; k < S; k++) {
            a0[k] = fmaf(tanhf_a(al[k] * al[k]), wd0, a0[k]);
            a1[k] = fmaf(tanhf_a(ah[k] * ah[k]), wd1, a1[k]);
            float t = tanhf_a(al[k] * ah[k]);
            a0[k] = fmaf(t, wm0, a0[k]);
            a1[k] = fmaf(t, wm1, a1[k]);
        }

        // Keep m-loop rolled: body (~120 inst) stays in L0 I$.
        #pragma unroll 1
        for (int m = 1; m < 32; m++) {
            const bool lo = l < (l ^ m);
            const float2 w  = wlo[m - 1][l];
            const float2 w2 = wx[m - 1][l];
            #pragma unroll
            for (int k = 0; k < S; k++) {
                // lo-lo / hi-hi: one tanh per lane-pair, exchanged once.
                float send = lo ? ah[k] : al[k];
                float x    = __shfl_xor_sync(0xffffffffu, send, m);
                float sc   = lo ? al[k] : ah[k];
                float t    = tanhf_a(sc * x);
                float to   = __shfl_xor_sync(0xffffffffu, t, m);
                float tl_  = lo ? t : to;   // T[l][l^m]
                float th_  = lo ? to : t;   // T[l+32][(l^m)+32]
                a0[k] = fmaf(tl_, w.x, a0[k]);
                a1[k] = fmaf(th_, w.y, a1[k]);
                // cross-half: T[l][(l^m)+32]; partner's value covers T[l+32][l^m].
                float xh = __shfl_xor_sync(0xffffffffu, ah[k], m);
                float ta = tanhf_a(al[k] * xh);
                float tb = __shfl_xor_sync(0xffffffffu, ta, m);
                a0[k] = fmaf(ta, w2.x, a0[k]);
                a1[k] = fmaf(tb, w2.y, a1[k]);
            }
        }

        #pragma unroll
        for (int k = 0; k < S; k++) {
            int b = base + k;
            if (b < B) {
                out[b * 64 + l]      = 0.1f * fmaxf(a0[k], 0.0f);
                out[b * 64 + 32 + l] = 0.1f * fmaxf(a1[k], 0.0f);
            }
        }
    }
}

extern "C" void kernel_launch(void* const* d_in, const int* in_sizes, int n_in,
                              void* d_out, int out_size) {
    const float* f1  = (const float*)d_in[0];
    const float* f2  = (const float*)d_in[1];
    const float* Wca = (const float*)d_in[2];
    const float* Wcv = (const float*)d_in[3];
    float* out = (float*)d_out;

    const int B = in_sizes[0] / 32;

    void* ctr = nullptr;
    cudaGetSymbolAddress(&ctr, g_cam_counter);
    cudaMemsetAsync(ctr, 0, sizeof(int));

    // One resident wave: 148 SMs x 8 blocks x 4 warps = 4736 warps.
    cam_kernel<<<1184, 128>>>(f1, f2, Wca, Wcv, out, B);
}